// round 15
// baseline (speedup 1.0000x reference)
#include <cuda_runtime.h>
#include <cuda_fp16.h>
#include <cstdint>

#define NPTS 100000
#define K3   27
#define MT   128
#define NTHR 256            // 8 warps: 4(M) x 2(N)
// stage (bytes): [A: 128 rows x 144B | B: 64 rows x 144B]; row = 128B data + 16B pad
#define STGB  27648
#define BOFFB 18432
#define SMEM_BYTES (4*STGB)   // 110592 -> still 2 CTAs/SM (221KB < 228KB)

// ---------------- device scratch ----------------
__device__ __align__(16) unsigned g_x16[(size_t)NPTS * 64];   // x fp16x2 words
__device__ __align__(16) unsigned g_h16[(size_t)NPTS * 64];   // h fp16x2 words [h0|h1]
// weight chunk images, 2304 words each, linear in stage index: base + s*2304
__device__ __align__(16) unsigned g_W00p[K3 * 4608];
__device__ __align__(16) unsigned g_Wcat[K3 * 4608];
__device__ __align__(16) unsigned g_W10p[4608];
__device__ __align__(16) unsigned g_W12p[2304];

// ---------------- helpers ----------------
__device__ __forceinline__ unsigned smem_u32(const void* p) {
    unsigned a;
    asm("{ .reg .u64 t; cvta.to.shared.u64 t, %1; cvt.u32.u64 %0, t; }" : "=r"(a) : "l"(p));
    return a;
}
__device__ __forceinline__ void cp16(unsigned dst, const void* src, unsigned srcsize) {
    asm volatile("cp.async.cg.shared.global [%0], [%1], 16, %2;"
                 :: "r"(dst), "l"(src), "r"(srcsize));
}
#define CP_COMMIT() asm volatile("cp.async.commit_group;")
#define CP_WAIT2()  asm volatile("cp.async.wait_group 2;")
#define CP_WAIT1()  asm volatile("cp.async.wait_group 1;")
#define CP_WAIT0()  asm volatile("cp.async.wait_group 0;")

__device__ __forceinline__ void ldsm4(unsigned& r0, unsigned& r1, unsigned& r2, unsigned& r3,
                                      unsigned a) {
    asm volatile("ldmatrix.sync.aligned.m8n8.x4.shared.b16 {%0,%1,%2,%3}, [%4];"
                 : "=r"(r0), "=r"(r1), "=r"(r2), "=r"(r3) : "r"(a));
}
__device__ __forceinline__ void mma_f16(float* d, const unsigned* a, unsigned b0, unsigned b1) {
    asm volatile(
        "mma.sync.aligned.m16n8k16.row.col.f32.f16.f16.f32 "
        "{%0,%1,%2,%3}, {%4,%5,%6,%7}, {%8,%9}, {%0,%1,%2,%3};\n"
        : "+f"(d[0]), "+f"(d[1]), "+f"(d[2]), "+f"(d[3])
        : "r"(a[0]), "r"(a[1]), "r"(a[2]), "r"(a[3]), "r"(b0), "r"(b1));
}
__device__ __forceinline__ unsigned packh2(float a, float b) {
    __half2 h = __floats2half2_rn(a, b);
    return *(unsigned*)&h;
}
__device__ __forceinline__ void wput(unsigned* arr, int word, int slot, float v) {
    ((__half*)arr)[(size_t)word * 2 + slot] = __float2half_rn(v);
}

// ---------------- prep kernels ----------------
__global__ void split_x(const float* __restrict__ x) {
    size_t t = (size_t)blockIdx.x * blockDim.x + threadIdx.x;
    if (t >= (size_t)NPTS * 32) return;
    float4 v = ((const float4*)x)[t];
    ((uint2*)g_x16)[t] = make_uint2(packh2(v.x, v.y), packh2(v.z, v.w));
}

#define P_W00  (K3 * 128 * 64)
#define P_WCAT (K3 * 64 * 128)
#define P_TOT  (P_W00 + P_WCAT + 128*64 + 64*64)

__global__ void pack_weights(const float* __restrict__ W00, const float* __restrict__ W01,
                             const float* __restrict__ W11, const float* __restrict__ W10,
                             const float* __restrict__ W12) {
    int t = blockIdx.x * blockDim.x + threadIdx.x;
    if (t < P_W00) {                       // W00[k][c 0..127][n 0..63]
        int k = t / 8192, rem = t % 8192, c = rem / 64, n = rem % 64;
        wput(g_W00p + k * 4608 + (c >> 6) * 2304, n * 36 + ((c & 63) >> 1), c & 1, W00[t]);
        return;
    }
    t -= P_W00;
    if (t < P_WCAT) {                      // half0 = W01, half1 = W11; c 0..63
        int k = t / 8192, rem = t % 8192, half = rem / 4096, r2 = rem % 4096;
        int c = r2 / 64, n = r2 % 64;
        float v = half ? W11[k * 4096 + c * 64 + n] : W01[k * 4096 + c * 64 + n];
        wput(g_Wcat + k * 4608 + half * 2304, n * 36 + (c >> 1), c & 1, v);
        return;
    }
    t -= P_WCAT;
    if (t < 128 * 64) {                    // W10[c 0..127][n]
        int c = t / 64, n = t % 64;
        wput(g_W10p + (c >> 6) * 2304, n * 36 + ((c & 63) >> 1), c & 1, W10[t]);
        return;
    }
    t -= 128 * 64;
    if (t < 64 * 64) {
        int c = t / 64, n = t % 64;
        wput(g_W12p, n * 36 + (c >> 1), c & 1, W12[t]);
    }
}

// ---- inner stage: [128m x 64k] x [64k x 64n] fp16, warp-phase-skewed k order ----
__device__ __forceinline__ void mma_stage(unsigned Ab, float acc[2][4][4],
                                          unsigned aOff, unsigned bOff, unsigned phB) {
    const unsigned Bb = Ab + BOFFB;
    #pragma unroll
    for (int g = 0; g < 4; ++g) {
        const unsigned go = (g * 32 + phB) & 127;   // warp-dependent k-group rotation
        unsigned a[2][4], b[2][4];
        #pragma unroll
        for (int mb = 0; mb < 2; ++mb)
            ldsm4(a[mb][0], a[mb][1], a[mb][2], a[mb][3], Ab + aOff + go + mb * 2304);
        #pragma unroll
        for (int p = 0; p < 2; ++p)
            ldsm4(b[p][0], b[p][1], b[p][2], b[p][3], Bb + bOff + go + p * 2304);
        #pragma unroll
        for (int mb = 0; mb < 2; ++mb)
            #pragma unroll
            for (int nt = 0; nt < 4; ++nt) {
                const int p = nt >> 1, u = (nt & 1) * 2;
                mma_f16(acc[mb][nt], a[mb], b[p][u], b[p][u + 1]);
            }
    }
}

// =============== kernel A: h = [ relu(conv0_0(x)+b00) | relu(x@W10+b10) ] ===============
__global__ __launch_bounds__(NTHR, 2)
void convA(const int* __restrict__ nbr,
           const float* __restrict__ b00, const float* __restrict__ b10) {
    extern __shared__ unsigned sm[];
    const unsigned sStg = smem_u32(sm);
    const int tid = threadIdx.x, lane = tid & 31, warp = tid >> 5;
    const int wm = warp >> 1, wn = warp & 1;
    const int base = blockIdx.x * MT, rows = min(MT, NPTS - base);
    const int r = tid >> 1, q = tid & 1;
    const bool inval = (r >= rows);
    const int* nbrP = nbr + (size_t)(base + (inval ? 0 : r)) * K3;
    const int selfIdx = inval ? NPTS : (base + r);

    const unsigned aOff = (unsigned)((wm*32 + ((lane>>3)&1)*8 + (lane&7))*144 + ((lane>>4)&1)*16);
    const unsigned bOff = (unsigned)((wn*32 + ((lane>>4)&1)*8 + (lane&7))*144 + ((lane>>3)&1)*16);
    const unsigned phB = (unsigned)(warp & 3) * 32u;
    const unsigned dA0 = sStg + (unsigned)(r*144 + q*64);
    const int qw = q * 16;

    auto stage = [&](unsigned bufD, int kcw, const unsigned* wsrc, int idx) {
        const unsigned sz = (idx < NPTS) ? 16u : 0u;
        const unsigned* src = g_x16 + (size_t)(unsigned)idx * 64u + kcw + qw;
        const unsigned dA = dA0 + bufD;
        cp16(dA,      src,      sz);
        cp16(dA + 16, src + 4,  sz);
        cp16(dA + 32, src + 8,  sz);
        cp16(dA + 48, src + 12, sz);
        const unsigned wD = sStg + bufD + BOFFB + (unsigned)tid * 16u;
        const unsigned* ws = wsrc + tid * 4;
        cp16(wD,            ws,            16u);
        cp16(wD + 256*16u,  ws + 256*4,    16u);
        if (tid < 64) cp16(wD + 512*16u, ws + 512*4, 16u);
        CP_COMMIT();
    };

    float acc0[2][4][4] = {};
    float acc1[2][4][4] = {};

    int id0 = inval ? NPTS : __ldg(&nbrP[0]);
    int idA = inval ? NPTS : __ldg(&nbrP[1]);
    int idB = inval ? NPTS : __ldg(&nbrP[2]);
    stage(0,      0,  g_W00p,          id0);   // stage 0 (tap 0, kc0)
    stage(STGB,   32, g_W00p + 2304,   id0);   // stage 1 (tap 0, kc1)
    stage(2*STGB, 0,  g_W00p + 4608,   idA);   // stage 2 (tap 1, kc0)

    const unsigned* wp = g_W00p + 3 * 2304;
    for (int it = 0; it < 12; ++it) {
        // u=0: mma s=4it (buf0), stage 4it+3 (buf3, kc1, tap 2it+1)
        CP_WAIT2(); __syncthreads();
        int idC = inval ? NPTS : __ldg(&nbrP[2*it + 3]);
        stage(3*STGB, 32, wp, idA);
        mma_stage(sStg,          acc0, aOff, bOff, phB);
        // u=1: mma 4it+1 (buf1), stage 4it+4 (buf0, kc0, tap 2it+2)
        CP_WAIT2(); __syncthreads();
        int idN = inval ? NPTS : __ldg(&nbrP[2*it + 4]);
        stage(0, 0, wp + 2304, idB);
        mma_stage(sStg + STGB,   acc0, aOff, bOff, phB);
        // u=2: mma 4it+2 (buf2), stage 4it+5 (buf1, kc1, tap 2it+2)
        CP_WAIT2(); __syncthreads();
        stage(STGB, 32, wp + 2*2304, idB);
        mma_stage(sStg + 2*STGB, acc0, aOff, bOff, phB);
        // u=3: mma 4it+3 (buf3), stage 4it+6 (buf2, kc0, tap 2it+3)
        CP_WAIT2(); __syncthreads();
        stage(2*STGB, 0, wp + 3*2304, idC);
        mma_stage(sStg + 3*STGB, acc0, aOff, bOff, phB);
        idA = idC; idB = idN;
        wp += 4 * 2304;
    }
    // tail: mma 48..55, stage 51..55 (idA = tap25, idB = tap26)
    CP_WAIT2(); __syncthreads();                               // s=48
    stage(3*STGB, 32, g_W00p + 51*2304, idA);
    mma_stage(sStg,          acc0, aOff, bOff, phB);
    CP_WAIT2(); __syncthreads();                               // s=49
    stage(0, 0, g_W00p + 52*2304, idB);
    mma_stage(sStg + STGB,   acc0, aOff, bOff, phB);
    CP_WAIT2(); __syncthreads();                               // s=50
    stage(STGB, 32, g_W00p + 53*2304, idB);
    mma_stage(sStg + 2*STGB, acc0, aOff, bOff, phB);
    CP_WAIT2(); __syncthreads();                               // s=51
    stage(2*STGB, 0, g_W10p, selfIdx);
    mma_stage(sStg + 3*STGB, acc0, aOff, bOff, phB);
    CP_WAIT2(); __syncthreads();                               // s=52
    stage(3*STGB, 32, g_W10p + 2304, selfIdx);
    mma_stage(sStg,          acc0, aOff, bOff, phB);
    CP_WAIT2(); __syncthreads();                               // s=53
    mma_stage(sStg + STGB,   acc0, aOff, bOff, phB);
    CP_WAIT1(); __syncthreads();                               // s=54
    mma_stage(sStg + 2*STGB, acc1, aOff, bOff, phB);
    CP_WAIT0(); __syncthreads();                               // s=55
    mma_stage(sStg + 3*STGB, acc1, aOff, bOff, phB);

    // epilogue: relu + bias -> h fp16
    #pragma unroll
    for (int mb = 0; mb < 2; ++mb) {
        const int r0 = wm * 32 + mb * 16 + (lane >> 2);
        const int p0 = base + r0, p1 = p0 + 8;
        #pragma unroll
        for (int nt = 0; nt < 4; ++nt) {
            const int col = wn * 32 + nt * 8 + (lane & 3) * 2;
            const float ba0 = __ldg(&b00[col]), ba1 = __ldg(&b00[col + 1]);
            const float bb0 = __ldg(&b10[col]), bb1 = __ldg(&b10[col + 1]);
            if (p0 < NPTS) {
                g_h16[(size_t)p0 * 64 + (col >> 1)] =
                    packh2(fmaxf(acc0[mb][nt][0] + ba0, 0.f), fmaxf(acc0[mb][nt][1] + ba1, 0.f));
                g_h16[(size_t)p0 * 64 + 32 + (col >> 1)] =
                    packh2(fmaxf(acc1[mb][nt][0] + bb0, 0.f), fmaxf(acc1[mb][nt][1] + bb1, 0.f));
            }
            if (p1 < NPTS) {
                g_h16[(size_t)p1 * 64 + (col >> 1)] =
                    packh2(fmaxf(acc0[mb][nt][2] + ba0, 0.f), fmaxf(acc0[mb][nt][3] + ba1, 0.f));
                g_h16[(size_t)p1 * 64 + 32 + (col >> 1)] =
                    packh2(fmaxf(acc1[mb][nt][2] + bb0, 0.f), fmaxf(acc1[mb][nt][3] + bb1, 0.f));
            }
        }
    }
}

// ==== kernel B: out = [conv0_1(h0)+b01 | relu(conv1_1(h1)+b11)@W12+b12] + x ====
__global__ __launch_bounds__(NTHR, 2)
void convB(const int* __restrict__ nbr,
           const float* __restrict__ b01, const float* __restrict__ b11,
           const float* __restrict__ b12, const float* __restrict__ x,
           float* __restrict__ out) {
    extern __shared__ unsigned sm[];
    const unsigned sStg = smem_u32(sm);
    const int tid = threadIdx.x, lane = tid & 31, warp = tid >> 5;
    const int wm = warp >> 1, wn = warp & 1;
    const int base = blockIdx.x * MT, rows = min(MT, NPTS - base);
    const int r = tid >> 1, q = tid & 1;
    const bool inval = (r >= rows);
    const int* nbrP = nbr + (size_t)(base + (inval ? 0 : r)) * K3;

    const unsigned aOff = (unsigned)((wm*32 + ((lane>>3)&1)*8 + (lane&7))*144 + ((lane>>4)&1)*16);
    const unsigned bOff = (unsigned)((wn*32 + ((lane>>4)&1)*8 + (lane&7))*144 + ((lane>>3)&1)*16);
    const unsigned phB = (unsigned)(warp & 3) * 32u;
    const unsigned dA0 = sStg + (unsigned)(r*144 + q*64);
    const int qw = q * 16;

    auto stage = [&](unsigned bufD, int kcw, const unsigned* wsrc, int idx) {
        const unsigned sz = (idx < NPTS) ? 16u : 0u;
        const unsigned* src = g_h16 + (size_t)(unsigned)idx * 64u + kcw + qw;
        const unsigned dA = dA0 + bufD;
        cp16(dA,      src,      sz);
        cp16(dA + 16, src + 4,  sz);
        cp16(dA + 32, src + 8,  sz);
        cp16(dA + 48, src + 12, sz);
        const unsigned wD = sStg + bufD + BOFFB + (unsigned)tid * 16u;
        const unsigned* ws = wsrc + tid * 4;
        cp16(wD,           ws,         16u);
        cp16(wD + 256*16u, ws + 256*4, 16u);
        if (tid < 64) cp16(wD + 512*16u, ws + 512*4, 16u);
        CP_COMMIT();
    };

    float acc0[2][4][4] = {};
    float acc1[2][4][4] = {};

    int id0 = inval ? NPTS : __ldg(&nbrP[0]);
    int idA = inval ? NPTS : __ldg(&nbrP[1]);
    int idB = inval ? NPTS : __ldg(&nbrP[2]);
    stage(0,      0,  g_Wcat,        id0);
    stage(STGB,   32, g_Wcat + 2304, id0);
    stage(2*STGB, 0,  g_Wcat + 4608, idA);

    const unsigned* wp = g_Wcat + 3 * 2304;
    for (int it = 0; it < 12; ++it) {
        CP_WAIT2(); __syncthreads();
        int idC = inval ? NPTS : __ldg(&nbrP[2*it + 3]);
        stage(3*STGB, 32, wp, idA);
        mma_stage(sStg,          acc0, aOff, bOff, phB);
        CP_WAIT2(); __syncthreads();
        int idN = inval ? NPTS : __ldg(&nbrP[2*it + 4]);
        stage(0, 0, wp + 2304, idB);
        mma_stage(sStg + STGB,   acc1, aOff, bOff, phB);
        CP_WAIT2(); __syncthreads();
        stage(STGB, 32, wp + 2*2304, idB);
        mma_stage(sStg + 2*STGB, acc0, aOff, bOff, phB);
        CP_WAIT2(); __syncthreads();
        stage(2*STGB, 0, wp + 3*2304, idC);
        mma_stage(sStg + 3*STGB, acc1, aOff, bOff, phB);
        idA = idC; idB = idN;
        wp += 4 * 2304;
    }
    // tail: mma 48..53, stage 51..53 (idA = tap25, idB = tap26)
    CP_WAIT2(); __syncthreads();                               // s=48
    stage(3*STGB, 32, g_Wcat + 51*2304, idA);
    mma_stage(sStg,          acc0, aOff, bOff, phB);
    CP_WAIT2(); __syncthreads();                               // s=49
    stage(0, 0, g_Wcat + 52*2304, idB);
    mma_stage(sStg + STGB,   acc1, aOff, bOff, phB);
    CP_WAIT2(); __syncthreads();                               // s=50
    stage(STGB, 32, g_Wcat + 53*2304, idB);
    mma_stage(sStg + 2*STGB, acc0, aOff, bOff, phB);
    CP_WAIT2(); __syncthreads();                               // s=51
    mma_stage(sStg + 3*STGB, acc1, aOff, bOff, phB);
    CP_WAIT1(); __syncthreads();                               // s=52
    mma_stage(sStg,          acc0, aOff, bOff, phB);
    CP_WAIT0(); __syncthreads();                               // s=53
    mma_stage(sStg + STGB,   acc1, aOff, bOff, phB);

    // ---- epilogue: store out0 (+b01 +x); stage h1b = relu(acc1+b11) fp16 into buf0 A ----
    #pragma unroll
    for (int mb = 0; mb < 2; ++mb) {
        const int r0 = wm * 32 + mb * 16 + (lane >> 2), r1 = r0 + 8;
        const int p0 = base + r0, p1 = base + r1;
        #pragma unroll
        for (int nt = 0; nt < 4; ++nt) {
            const int col = wn * 32 + nt * 8 + (lane & 3) * 2;
            const float bh0 = __ldg(&b11[col]), bh1 = __ldg(&b11[col + 1]);
            sm[r0 * 36 + (col >> 1)] =
                packh2(fmaxf(acc1[mb][nt][0] + bh0, 0.f), fmaxf(acc1[mb][nt][1] + bh1, 0.f));
            sm[r1 * 36 + (col >> 1)] =
                packh2(fmaxf(acc1[mb][nt][2] + bh0, 0.f), fmaxf(acc1[mb][nt][3] + bh1, 0.f));
            const float bo0 = __ldg(&b01[col]), bo1 = __ldg(&b01[col + 1]);
            if (p0 < NPTS) {
                float2 xv = *(const float2*)(x + (size_t)p0 * 128 + col);
                *(float2*)(out + (size_t)p0 * 128 + col) =
                    make_float2(acc0[mb][nt][0] + bo0 + xv.x, acc0[mb][nt][1] + bo1 + xv.y);
            }
            if (p1 < NPTS) {
                float2 xv = *(const float2*)(x + (size_t)p1 * 128 + col);
                *(float2*)(out + (size_t)p1 * 128 + col) =
                    make_float2(acc0[mb][nt][2] + bo0 + xv.x, acc0[mb][nt][3] + bo1 + xv.y);
            }
        }
    }
    // copy W12 chunk image into buf0 B region
    #pragma unroll
    for (int j = 0; j < 3; ++j) {
        const int i = j * NTHR + tid;
        if (i < 576) ((uint4*)(sm + BOFFB / 4))[i] = ((const uint4*)g_W12p)[i];
    }
    __syncthreads();

    // ---- 1x1 epilogue GEMM: acc2 = h1b @ W12 ----
    float acc2[2][4][4] = {};
    mma_stage(sStg, acc2, aOff, bOff, phB);

    #pragma unroll
    for (int mb = 0; mb < 2; ++mb) {
        const int r0 = wm * 32 + mb * 16 + (lane >> 2);
        const int p0 = base + r0, p1 = p0 + 8;
        #pragma unroll
        for (int nt = 0; nt < 4; ++nt) {
            const int col = wn * 32 + nt * 8 + (lane & 3) * 2;
            const float bv0 = __ldg(&b12[col]), bv1 = __ldg(&b12[col + 1]);
            if (p0 < NPTS) {
                float2 xv = *(const float2*)(x + (size_t)p0 * 128 + 64 + col);
                *(float2*)(out + (size_t)p0 * 128 + 64 + col) =
                    make_float2(acc2[mb][nt][0] + bv0 + xv.x, acc2[mb][nt][1] + bv1 + xv.y);
            }
            if (p1 < NPTS) {
                float2 xv = *(const float2*)(x + (size_t)p1 * 128 + 64 + col);
                *(float2*)(out + (size_t)p1 * 128 + 64 + col) =
                    make_float2(acc2[mb][nt][2] + bv0 + xv.x, acc2[mb][nt][3] + bv1 + xv.y);
            }
        }
    }
}

// ---------------- launch ----------------
extern "C" void kernel_launch(void* const* d_in, const int* in_sizes, int n_in,
                              void* d_out, int out_size) {
    const float* x   = (const float*)d_in[0];
    const int*   nbr = (const int*)  d_in[1];
    const float* W00 = (const float*)d_in[2];
    const float* b00 = (const float*)d_in[3];
    const float* W01 = (const float*)d_in[4];
    const float* b01 = (const float*)d_in[5];
    const float* W10 = (const float*)d_in[6];
    const float* b10 = (const float*)d_in[7];
    const float* W11 = (const float*)d_in[8];
    const float* b11 = (const float*)d_in[9];
    const float* W12 = (const float*)d_in[10];
    const float* b12 = (const float*)d_in[11];
    float* out = (float*)d_out;

    cudaFuncSetAttribute(convA, cudaFuncAttributeMaxDynamicSharedMemorySize, SMEM_BYTES);
    cudaFuncSetAttribute(convB, cudaFuncAttributeMaxDynamicSharedMemorySize, SMEM_BYTES);

    split_x<<<(NPTS * 32 + 255) / 256, 256>>>(x);
    pack_weights<<<(P_TOT + 255) / 256, 256>>>(W00, W01, W11, W10, W12);
    const int grid = (NPTS + MT - 1) / MT;   // 782
    convA<<<grid, NTHR, SMEM_BYTES>>>(nbr, b00, b10);
    convB<<<grid, NTHR, SMEM_BYTES>>>(nbr, b01, b11, b12, x, out);
}

// round 16
// speedup vs baseline: 1.0035x; 1.0035x over previous
#include <cuda_runtime.h>
#include <cuda_fp16.h>
#include <cstdint>

#define NPTS 100000
#define K3   27
#define MT   128
#define NTHR 256            // 8 warps: 4(M) x 2(N)
// stage (bytes): [A: 128 rows x 144B | B: 64 rows x 144B]; row = 128B data + 16B pad
#define STGB  27648
#define BOFFB 18432
#define SMEM_BYTES (4*STGB)   // 110592 -> still 2 CTAs/SM (221KB < 228KB)

// ---------------- device scratch ----------------
__device__ __align__(16) unsigned g_x16[(size_t)NPTS * 64];   // x fp16x2 words
__device__ __align__(16) unsigned g_h16[(size_t)NPTS * 64];   // h fp16x2 words [h0|h1]
// weight chunk images, 2304 words each, linear in stage index: base + s*2304
__device__ __align__(16) unsigned g_W00p[K3 * 4608];
__device__ __align__(16) unsigned g_Wcat[K3 * 4608];
__device__ __align__(16) unsigned g_W10p[4608];
__device__ __align__(16) unsigned g_W12p[2304];

// ---------------- helpers ----------------
__device__ __forceinline__ unsigned smem_u32(const void* p) {
    unsigned a;
    asm("{ .reg .u64 t; cvta.to.shared.u64 t, %1; cvt.u32.u64 %0, t; }" : "=r"(a) : "l"(p));
    return a;
}
__device__ __forceinline__ void cp16(unsigned dst, const void* src, unsigned srcsize) {
    asm volatile("cp.async.cg.shared.global [%0], [%1], 16, %2;"
                 :: "r"(dst), "l"(src), "r"(srcsize));
}
#define CP_COMMIT() asm volatile("cp.async.commit_group;")
#define CP_WAIT2()  asm volatile("cp.async.wait_group 2;")
#define CP_WAIT1()  asm volatile("cp.async.wait_group 1;")
#define CP_WAIT0()  asm volatile("cp.async.wait_group 0;")

__device__ __forceinline__ void ldsm4(unsigned& r0, unsigned& r1, unsigned& r2, unsigned& r3,
                                      unsigned a) {
    asm volatile("ldmatrix.sync.aligned.m8n8.x4.shared.b16 {%0,%1,%2,%3}, [%4];"
                 : "=r"(r0), "=r"(r1), "=r"(r2), "=r"(r3) : "r"(a));
}
__device__ __forceinline__ void mma_f16(float* d, const unsigned* a, unsigned b0, unsigned b1) {
    asm volatile(
        "mma.sync.aligned.m16n8k16.row.col.f32.f16.f16.f32 "
        "{%0,%1,%2,%3}, {%4,%5,%6,%7}, {%8,%9}, {%0,%1,%2,%3};\n"
        : "+f"(d[0]), "+f"(d[1]), "+f"(d[2]), "+f"(d[3])
        : "r"(a[0]), "r"(a[1]), "r"(a[2]), "r"(a[3]), "r"(b0), "r"(b1));
}
__device__ __forceinline__ unsigned packh2(float a, float b) {
    __half2 h = __floats2half2_rn(a, b);
    return *(unsigned*)&h;
}
__device__ __forceinline__ void wput(unsigned* arr, int word, int slot, float v) {
    ((__half*)arr)[(size_t)word * 2 + slot] = __float2half_rn(v);
}

// ---------------- prep kernels ----------------
__global__ void split_x(const float* __restrict__ x) {
    size_t t = (size_t)blockIdx.x * blockDim.x + threadIdx.x;
    if (t >= (size_t)NPTS * 32) return;
    float4 v = ((const float4*)x)[t];
    ((uint2*)g_x16)[t] = make_uint2(packh2(v.x, v.y), packh2(v.z, v.w));
}

#define P_W00  (K3 * 128 * 64)
#define P_WCAT (K3 * 64 * 128)
#define P_TOT  (P_W00 + P_WCAT + 128*64 + 64*64)

__global__ void pack_weights(const float* __restrict__ W00, const float* __restrict__ W01,
                             const float* __restrict__ W11, const float* __restrict__ W10,
                             const float* __restrict__ W12) {
    int t = blockIdx.x * blockDim.x + threadIdx.x;
    if (t < P_W00) {                       // W00[k][c 0..127][n 0..63]
        int k = t / 8192, rem = t % 8192, c = rem / 64, n = rem % 64;
        wput(g_W00p + k * 4608 + (c >> 6) * 2304, n * 36 + ((c & 63) >> 1), c & 1, W00[t]);
        return;
    }
    t -= P_W00;
    if (t < P_WCAT) {                      // half0 = W01, half1 = W11; c 0..63
        int k = t / 8192, rem = t % 8192, half = rem / 4096, r2 = rem % 4096;
        int c = r2 / 64, n = r2 % 64;
        float v = half ? W11[k * 4096 + c * 64 + n] : W01[k * 4096 + c * 64 + n];
        wput(g_Wcat + k * 4608 + half * 2304, n * 36 + (c >> 1), c & 1, v);
        return;
    }
    t -= P_WCAT;
    if (t < 128 * 64) {                    // W10[c 0..127][n]
        int c = t / 64, n = t % 64;
        wput(g_W10p + (c >> 6) * 2304, n * 36 + ((c & 63) >> 1), c & 1, W10[t]);
        return;
    }
    t -= 128 * 64;
    if (t < 64 * 64) {
        int c = t / 64, n = t % 64;
        wput(g_W12p, n * 36 + (c >> 1), c & 1, W12[t]);
    }
}

// ---- inner stage: [128m x 64k] x [64k x 64n] fp16, warp-phase-skewed k order ----
__device__ __forceinline__ void mma_stage(unsigned Ab, float acc[2][4][4],
                                          unsigned aOff, unsigned bOff, unsigned phB) {
    const unsigned Bb = Ab + BOFFB;
    #pragma unroll
    for (int g = 0; g < 4; ++g) {
        const unsigned go = (g * 32 + phB) & 127;   // warp-dependent k-group rotation
        unsigned a[2][4], b[2][4];
        #pragma unroll
        for (int mb = 0; mb < 2; ++mb)
            ldsm4(a[mb][0], a[mb][1], a[mb][2], a[mb][3], Ab + aOff + go + mb * 2304);
        #pragma unroll
        for (int p = 0; p < 2; ++p)
            ldsm4(b[p][0], b[p][1], b[p][2], b[p][3], Bb + bOff + go + p * 2304);
        #pragma unroll
        for (int mb = 0; mb < 2; ++mb)
            #pragma unroll
            for (int nt = 0; nt < 4; ++nt) {
                const int p = nt >> 1, u = (nt & 1) * 2;
                mma_f16(acc[mb][nt], a[mb], b[p][u], b[p][u + 1]);
            }
    }
}

// =============== kernel A: h = [ relu(conv0_0(x)+b00) | relu(x@W10+b10) ] ===============
__global__ __launch_bounds__(NTHR, 2)
void convA(const int* __restrict__ nbr,
           const float* __restrict__ b00, const float* __restrict__ b10) {
    extern __shared__ unsigned sm[];
    const unsigned sStg = smem_u32(sm);
    const int tid = threadIdx.x, lane = tid & 31, warp = tid >> 5;
    const int wm = warp >> 1, wn = warp & 1;
    const int base = blockIdx.x * MT, rows = min(MT, NPTS - base);
    const int r = tid >> 1, q = tid & 1;
    const bool inval = (r >= rows);
    const int* nbrP = nbr + (size_t)(base + (inval ? 0 : r)) * K3;
    const int selfIdx = inval ? NPTS : (base + r);

    const unsigned aOff = (unsigned)((wm*32 + ((lane>>3)&1)*8 + (lane&7))*144 + ((lane>>4)&1)*16);
    const unsigned bOff = (unsigned)((wn*32 + ((lane>>4)&1)*8 + (lane&7))*144 + ((lane>>3)&1)*16);
    const unsigned phB = (unsigned)(warp & 3) * 32u;
    const unsigned dA0 = sStg + (unsigned)(r*144 + q*64);
    const int qw = q * 16;

    auto stage = [&](unsigned bufD, int kcw, const unsigned* wsrc, int idx) {
        const unsigned sz = (idx < NPTS) ? 16u : 0u;
        const unsigned* src = g_x16 + (size_t)(unsigned)idx * 64u + kcw + qw;
        const unsigned dA = dA0 + bufD;
        cp16(dA,      src,      sz);
        cp16(dA + 16, src + 4,  sz);
        cp16(dA + 32, src + 8,  sz);
        cp16(dA + 48, src + 12, sz);
        const unsigned wD = sStg + bufD + BOFFB + (unsigned)tid * 16u;
        const unsigned* ws = wsrc + tid * 4;
        cp16(wD,            ws,            16u);
        cp16(wD + 256*16u,  ws + 256*4,    16u);
        if (tid < 64) cp16(wD + 512*16u, ws + 512*4, 16u);
        CP_COMMIT();
    };

    float acc0[2][4][4] = {};
    float acc1[2][4][4] = {};

    int id0 = inval ? NPTS : __ldg(&nbrP[0]);
    int idA = inval ? NPTS : __ldg(&nbrP[1]);
    int idB = inval ? NPTS : __ldg(&nbrP[2]);
    stage(0,      0,  g_W00p,          id0);   // stage 0 (tap 0, kc0)
    stage(STGB,   32, g_W00p + 2304,   id0);   // stage 1 (tap 0, kc1)
    stage(2*STGB, 0,  g_W00p + 4608,   idA);   // stage 2 (tap 1, kc0)

    const unsigned* wp = g_W00p + 3 * 2304;
    for (int it = 0; it < 12; ++it) {
        // u=0: mma s=4it (buf0), stage 4it+3 (buf3, kc1, tap 2it+1)
        CP_WAIT2(); __syncthreads();
        int idC = inval ? NPTS : __ldg(&nbrP[2*it + 3]);
        stage(3*STGB, 32, wp, idA);
        mma_stage(sStg,          acc0, aOff, bOff, phB);
        // u=1: mma 4it+1 (buf1), stage 4it+4 (buf0, kc0, tap 2it+2)
        CP_WAIT2(); __syncthreads();
        int idN = inval ? NPTS : __ldg(&nbrP[2*it + 4]);
        stage(0, 0, wp + 2304, idB);
        mma_stage(sStg + STGB,   acc0, aOff, bOff, phB);
        // u=2: mma 4it+2 (buf2), stage 4it+5 (buf1, kc1, tap 2it+2)
        CP_WAIT2(); __syncthreads();
        stage(STGB, 32, wp + 2*2304, idB);
        mma_stage(sStg + 2*STGB, acc0, aOff, bOff, phB);
        // u=3: mma 4it+3 (buf3), stage 4it+6 (buf2, kc0, tap 2it+3)
        CP_WAIT2(); __syncthreads();
        stage(2*STGB, 0, wp + 3*2304, idC);
        mma_stage(sStg + 3*STGB, acc0, aOff, bOff, phB);
        idA = idC; idB = idN;
        wp += 4 * 2304;
    }
    // tail: mma 48..55, stage 51..55 (idA = tap25, idB = tap26)
    CP_WAIT2(); __syncthreads();                               // s=48
    stage(3*STGB, 32, g_W00p + 51*2304, idA);
    mma_stage(sStg,          acc0, aOff, bOff, phB);
    CP_WAIT2(); __syncthreads();                               // s=49
    stage(0, 0, g_W00p + 52*2304, idB);
    mma_stage(sStg + STGB,   acc0, aOff, bOff, phB);
    CP_WAIT2(); __syncthreads();                               // s=50
    stage(STGB, 32, g_W00p + 53*2304, idB);
    mma_stage(sStg + 2*STGB, acc0, aOff, bOff, phB);
    CP_WAIT2(); __syncthreads();                               // s=51
    stage(2*STGB, 0, g_W10p, selfIdx);
    mma_stage(sStg + 3*STGB, acc0, aOff, bOff, phB);
    CP_WAIT2(); __syncthreads();                               // s=52
    stage(3*STGB, 32, g_W10p + 2304, selfIdx);
    mma_stage(sStg,          acc0, aOff, bOff, phB);
    CP_WAIT2(); __syncthreads();                               // s=53
    mma_stage(sStg + STGB,   acc0, aOff, bOff, phB);
    CP_WAIT1(); __syncthreads();                               // s=54
    mma_stage(sStg + 2*STGB, acc1, aOff, bOff, phB);
    CP_WAIT0(); __syncthreads();                               // s=55
    mma_stage(sStg + 3*STGB, acc1, aOff, bOff, phB);

    // epilogue: relu + bias -> h fp16
    #pragma unroll
    for (int mb = 0; mb < 2; ++mb) {
        const int r0 = wm * 32 + mb * 16 + (lane >> 2);
        const int p0 = base + r0, p1 = p0 + 8;
        #pragma unroll
        for (int nt = 0; nt < 4; ++nt) {
            const int col = wn * 32 + nt * 8 + (lane & 3) * 2;
            const float ba0 = __ldg(&b00[col]), ba1 = __ldg(&b00[col + 1]);
            const float bb0 = __ldg(&b10[col]), bb1 = __ldg(&b10[col + 1]);
            if (p0 < NPTS) {
                g_h16[(size_t)p0 * 64 + (col >> 1)] =
                    packh2(fmaxf(acc0[mb][nt][0] + ba0, 0.f), fmaxf(acc0[mb][nt][1] + ba1, 0.f));
                g_h16[(size_t)p0 * 64 + 32 + (col >> 1)] =
                    packh2(fmaxf(acc1[mb][nt][0] + bb0, 0.f), fmaxf(acc1[mb][nt][1] + bb1, 0.f));
            }
            if (p1 < NPTS) {
                g_h16[(size_t)p1 * 64 + (col >> 1)] =
                    packh2(fmaxf(acc0[mb][nt][2] + ba0, 0.f), fmaxf(acc0[mb][nt][3] + ba1, 0.f));
                g_h16[(size_t)p1 * 64 + 32 + (col >> 1)] =
                    packh2(fmaxf(acc1[mb][nt][2] + bb0, 0.f), fmaxf(acc1[mb][nt][3] + bb1, 0.f));
            }
        }
    }
}

// ==== kernel B: out = [conv0_1(h0)+b01 | relu(conv1_1(h1)+b11)@W12+b12] + x ====
__global__ __launch_bounds__(NTHR, 2)
void convB(const int* __restrict__ nbr,
           const float* __restrict__ b01, const float* __restrict__ b11,
           const float* __restrict__ b12, const float* __restrict__ x,
           float* __restrict__ out) {
    extern __shared__ unsigned sm[];
    const unsigned sStg = smem_u32(sm);
    const int tid = threadIdx.x, lane = tid & 31, warp = tid >> 5;
    const int wm = warp >> 1, wn = warp & 1;
    const int base = blockIdx.x * MT, rows = min(MT, NPTS - base);
    const int r = tid >> 1, q = tid & 1;
    const bool inval = (r >= rows);
    const int* nbrP = nbr + (size_t)(base + (inval ? 0 : r)) * K3;

    const unsigned aOff = (unsigned)((wm*32 + ((lane>>3)&1)*8 + (lane&7))*144 + ((lane>>4)&1)*16);
    const unsigned bOff = (unsigned)((wn*32 + ((lane>>4)&1)*8 + (lane&7))*144 + ((lane>>3)&1)*16);
    const unsigned phB = (unsigned)(warp & 3) * 32u;
    const unsigned dA0 = sStg + (unsigned)(r*144 + q*64);
    const int qw = q * 16;

    auto stage = [&](unsigned bufD, int kcw, const unsigned* wsrc, int idx) {
        const unsigned sz = (idx < NPTS) ? 16u : 0u;
        const unsigned* src = g_h16 + (size_t)(unsigned)idx * 64u + kcw + qw;
        const unsigned dA = dA0 + bufD;
        cp16(dA,      src,      sz);
        cp16(dA + 16, src + 4,  sz);
        cp16(dA + 32, src + 8,  sz);
        cp16(dA + 48, src + 12, sz);
        const unsigned wD = sStg + bufD + BOFFB + (unsigned)tid * 16u;
        const unsigned* ws = wsrc + tid * 4;
        cp16(wD,           ws,         16u);
        cp16(wD + 256*16u, ws + 256*4, 16u);
        if (tid < 64) cp16(wD + 512*16u, ws + 512*4, 16u);
        CP_COMMIT();
    };

    float acc0[2][4][4] = {};
    float acc1[2][4][4] = {};

    int id0 = inval ? NPTS : __ldg(&nbrP[0]);
    int idA = inval ? NPTS : __ldg(&nbrP[1]);
    int idB = inval ? NPTS : __ldg(&nbrP[2]);
    stage(0,      0,  g_Wcat,        id0);
    stage(STGB,   32, g_Wcat + 2304, id0);
    stage(2*STGB, 0,  g_Wcat + 4608, idA);

    const unsigned* wp = g_Wcat + 3 * 2304;
    for (int it = 0; it < 12; ++it) {
        CP_WAIT2(); __syncthreads();
        int idC = inval ? NPTS : __ldg(&nbrP[2*it + 3]);
        stage(3*STGB, 32, wp, idA);
        mma_stage(sStg,          acc0, aOff, bOff, phB);
        CP_WAIT2(); __syncthreads();
        int idN = inval ? NPTS : __ldg(&nbrP[2*it + 4]);
        stage(0, 0, wp + 2304, idB);
        mma_stage(sStg + STGB,   acc1, aOff, bOff, phB);
        CP_WAIT2(); __syncthreads();
        stage(STGB, 32, wp + 2*2304, idB);
        mma_stage(sStg + 2*STGB, acc0, aOff, bOff, phB);
        CP_WAIT2(); __syncthreads();
        stage(2*STGB, 0, wp + 3*2304, idC);
        mma_stage(sStg + 3*STGB, acc1, aOff, bOff, phB);
        idA = idC; idB = idN;
        wp += 4 * 2304;
    }
    // tail: mma 48..53, stage 51..53 (idA = tap25, idB = tap26)
    CP_WAIT2(); __syncthreads();                               // s=48
    stage(3*STGB, 32, g_Wcat + 51*2304, idA);
    mma_stage(sStg,          acc0, aOff, bOff, phB);
    CP_WAIT2(); __syncthreads();                               // s=49
    stage(0, 0, g_Wcat + 52*2304, idB);
    mma_stage(sStg + STGB,   acc1, aOff, bOff, phB);
    CP_WAIT2(); __syncthreads();                               // s=50
    stage(STGB, 32, g_Wcat + 53*2304, idB);
    mma_stage(sStg + 2*STGB, acc0, aOff, bOff, phB);
    CP_WAIT2(); __syncthreads();                               // s=51
    mma_stage(sStg + 3*STGB, acc1, aOff, bOff, phB);
    CP_WAIT1(); __syncthreads();                               // s=52
    mma_stage(sStg,          acc0, aOff, bOff, phB);
    CP_WAIT0(); __syncthreads();                               // s=53
    mma_stage(sStg + STGB,   acc1, aOff, bOff, phB);

    // ---- epilogue: store out0 (+b01 +x); stage h1b = relu(acc1+b11) fp16 into buf0 A ----
    #pragma unroll
    for (int mb = 0; mb < 2; ++mb) {
        const int r0 = wm * 32 + mb * 16 + (lane >> 2), r1 = r0 + 8;
        const int p0 = base + r0, p1 = base + r1;
        #pragma unroll
        for (int nt = 0; nt < 4; ++nt) {
            const int col = wn * 32 + nt * 8 + (lane & 3) * 2;
            const float bh0 = __ldg(&b11[col]), bh1 = __ldg(&b11[col + 1]);
            sm[r0 * 36 + (col >> 1)] =
                packh2(fmaxf(acc1[mb][nt][0] + bh0, 0.f), fmaxf(acc1[mb][nt][1] + bh1, 0.f));
            sm[r1 * 36 + (col >> 1)] =
                packh2(fmaxf(acc1[mb][nt][2] + bh0, 0.f), fmaxf(acc1[mb][nt][3] + bh1, 0.f));
            const float bo0 = __ldg(&b01[col]), bo1 = __ldg(&b01[col + 1]);
            if (p0 < NPTS) {
                float2 xv = *(const float2*)(x + (size_t)p0 * 128 + col);
                *(float2*)(out + (size_t)p0 * 128 + col) =
                    make_float2(acc0[mb][nt][0] + bo0 + xv.x, acc0[mb][nt][1] + bo1 + xv.y);
            }
            if (p1 < NPTS) {
                float2 xv = *(const float2*)(x + (size_t)p1 * 128 + col);
                *(float2*)(out + (size_t)p1 * 128 + col) =
                    make_float2(acc0[mb][nt][2] + bo0 + xv.x, acc0[mb][nt][3] + bo1 + xv.y);
            }
        }
    }
    // copy W12 chunk image into buf0 B region
    #pragma unroll
    for (int j = 0; j < 3; ++j) {
        const int i = j * NTHR + tid;
        if (i < 576) ((uint4*)(sm + BOFFB / 4))[i] = ((const uint4*)g_W12p)[i];
    }
    __syncthreads();

    // ---- 1x1 epilogue GEMM: acc2 = h1b @ W12 ----
    float acc2[2][4][4] = {};
    mma_stage(sStg, acc2, aOff, bOff, phB);

    #pragma unroll
    for (int mb = 0; mb < 2; ++mb) {
        const int r0 = wm * 32 + mb * 16 + (lane >> 2);
        const int p0 = base + r0, p1 = p0 + 8;
        #pragma unroll
        for (int nt = 0; nt < 4; ++nt) {
            const int col = wn * 32 + nt * 8 + (lane & 3) * 2;
            const float bv0 = __ldg(&b12[col]), bv1 = __ldg(&b12[col + 1]);
            if (p0 < NPTS) {
                float2 xv = *(const float2*)(x + (size_t)p0 * 128 + 64 + col);
                *(float2*)(out + (size_t)p0 * 128 + 64 + col) =
                    make_float2(acc2[mb][nt][0] + bv0 + xv.x, acc2[mb][nt][1] + bv1 + xv.y);
            }
            if (p1 < NPTS) {
                float2 xv = *(const float2*)(x + (size_t)p1 * 128 + 64 + col);
                *(float2*)(out + (size_t)p1 * 128 + 64 + col) =
                    make_float2(acc2[mb][nt][2] + bv0 + xv.x, acc2[mb][nt][3] + bv1 + xv.y);
            }
        }
    }
}

// ---------------- launch ----------------
extern "C" void kernel_launch(void* const* d_in, const int* in_sizes, int n_in,
                              void* d_out, int out_size) {
    const float* x   = (const float*)d_in[0];
    const int*   nbr = (const int*)  d_in[1];
    const float* W00 = (const float*)d_in[2];
    const float* b00 = (const float*)d_in[3];
    const float* W01 = (const float*)d_in[4];
    const float* b01 = (const float*)d_in[5];
    const float* W10 = (const float*)d_in[6];
    const float* b10 = (const float*)d_in[7];
    const float* W11 = (const float*)d_in[8];
    const float* b11 = (const float*)d_in[9];
    const float* W12 = (const float*)d_in[10];
    const float* b12 = (const float*)d_in[11];
    float* out = (float*)d_out;

    cudaFuncSetAttribute(convA, cudaFuncAttributeMaxDynamicSharedMemorySize, SMEM_BYTES);
    cudaFuncSetAttribute(convB, cudaFuncAttributeMaxDynamicSharedMemorySize, SMEM_BYTES);

    split_x<<<(NPTS * 32 + 255) / 256, 256>>>(x);
    pack_weights<<<(P_TOT + 255) / 256, 256>>>(W00, W01, W11, W10, W12);
    const int grid = (NPTS + MT - 1) / MT;   // 782
    convA<<<grid, NTHR, SMEM_BYTES>>>(nbr, b00, b10);
    convB<<<grid, NTHR, SMEM_BYTES>>>(nbr, b01, b11, b12, x, out);
}

// round 17
// speedup vs baseline: 1.0035x; 1.0001x over previous
#include <cuda_runtime.h>
#include <cuda_fp16.h>
#include <cstdint>

#define NPTS 100000
#define K3   27
#define MT   128
#define NTHR 256            // 8 warps: 4(M) x 2(N)
// stage (bytes): [A: 128 rows x 144B | B: 64 rows x 144B]; row = 128B data + 16B pad
#define STGB  27648
#define BOFFB 18432
#define SMEM_BYTES (4*STGB)   // 110592 -> still 2 CTAs/SM (221KB < 228KB)

// ---------------- device scratch ----------------
__device__ __align__(16) unsigned g_x16[(size_t)NPTS * 64];   // x fp16x2 words
__device__ __align__(16) unsigned g_h16[(size_t)NPTS * 64];   // h fp16x2 words [h0|h1]
// weight chunk images, 2304 words each, linear in stage index: base + s*2304
__device__ __align__(16) unsigned g_W00p[K3 * 4608];
__device__ __align__(16) unsigned g_Wcat[K3 * 4608];
__device__ __align__(16) unsigned g_W10p[4608];
__device__ __align__(16) unsigned g_W12p[2304];

// ---------------- helpers ----------------
__device__ __forceinline__ unsigned smem_u32(const void* p) {
    unsigned a;
    asm("{ .reg .u64 t; cvta.to.shared.u64 t, %1; cvt.u32.u64 %0, t; }" : "=r"(a) : "l"(p));
    return a;
}
__device__ __forceinline__ void cp16(unsigned dst, const void* src, unsigned srcsize) {
    asm volatile("cp.async.cg.shared.global [%0], [%1], 16, %2;"
                 :: "r"(dst), "l"(src), "r"(srcsize));
}
#define CP_COMMIT() asm volatile("cp.async.commit_group;")
#define CP_WAIT2()  asm volatile("cp.async.wait_group 2;")
#define CP_WAIT1()  asm volatile("cp.async.wait_group 1;")
#define CP_WAIT0()  asm volatile("cp.async.wait_group 0;")

__device__ __forceinline__ void ldsm4(unsigned& r0, unsigned& r1, unsigned& r2, unsigned& r3,
                                      unsigned a) {
    asm volatile("ldmatrix.sync.aligned.m8n8.x4.shared.b16 {%0,%1,%2,%3}, [%4];"
                 : "=r"(r0), "=r"(r1), "=r"(r2), "=r"(r3) : "r"(a));
}
__device__ __forceinline__ void mma_f16(float* d, const unsigned* a, unsigned b0, unsigned b1) {
    asm volatile(
        "mma.sync.aligned.m16n8k16.row.col.f32.f16.f16.f32 "
        "{%0,%1,%2,%3}, {%4,%5,%6,%7}, {%8,%9}, {%0,%1,%2,%3};\n"
        : "+f"(d[0]), "+f"(d[1]), "+f"(d[2]), "+f"(d[3])
        : "r"(a[0]), "r"(a[1]), "r"(a[2]), "r"(a[3]), "r"(b0), "r"(b1));
}
__device__ __forceinline__ unsigned packh2(float a, float b) {
    __half2 h = __floats2half2_rn(a, b);
    return *(unsigned*)&h;
}
__device__ __forceinline__ void wput(unsigned* arr, int word, int slot, float v) {
    ((__half*)arr)[(size_t)word * 2 + slot] = __float2half_rn(v);
}

// ---------------- prep kernels ----------------
__global__ void split_x(const float* __restrict__ x) {
    size_t t = (size_t)blockIdx.x * blockDim.x + threadIdx.x;
    if (t >= (size_t)NPTS * 32) return;
    float4 v = ((const float4*)x)[t];
    ((uint2*)g_x16)[t] = make_uint2(packh2(v.x, v.y), packh2(v.z, v.w));
}

#define P_W00  (K3 * 128 * 64)
#define P_WCAT (K3 * 64 * 128)
#define P_TOT  (P_W00 + P_WCAT + 128*64 + 64*64)

__global__ void pack_weights(const float* __restrict__ W00, const float* __restrict__ W01,
                             const float* __restrict__ W11, const float* __restrict__ W10,
                             const float* __restrict__ W12) {
    int t = blockIdx.x * blockDim.x + threadIdx.x;
    if (t < P_W00) {                       // W00[k][c 0..127][n 0..63]
        int k = t / 8192, rem = t % 8192, c = rem / 64, n = rem % 64;
        wput(g_W00p + k * 4608 + (c >> 6) * 2304, n * 36 + ((c & 63) >> 1), c & 1, W00[t]);
        return;
    }
    t -= P_W00;
    if (t < P_WCAT) {                      // half0 = W01, half1 = W11; c 0..63
        int k = t / 8192, rem = t % 8192, half = rem / 4096, r2 = rem % 4096;
        int c = r2 / 64, n = r2 % 64;
        float v = half ? W11[k * 4096 + c * 64 + n] : W01[k * 4096 + c * 64 + n];
        wput(g_Wcat + k * 4608 + half * 2304, n * 36 + (c >> 1), c & 1, v);
        return;
    }
    t -= P_WCAT;
    if (t < 128 * 64) {                    // W10[c 0..127][n]
        int c = t / 64, n = t % 64;
        wput(g_W10p + (c >> 6) * 2304, n * 36 + ((c & 63) >> 1), c & 1, W10[t]);
        return;
    }
    t -= 128 * 64;
    if (t < 64 * 64) {
        int c = t / 64, n = t % 64;
        wput(g_W12p, n * 36 + (c >> 1), c & 1, W12[t]);
    }
}

// ---- inner stage: [128m x 64k] x [64k x 64n] fp16, warp-phase-skewed k order ----
__device__ __forceinline__ void mma_stage(unsigned Ab, float acc[2][4][4],
                                          unsigned aOff, unsigned bOff, unsigned phB) {
    const unsigned Bb = Ab + BOFFB;
    #pragma unroll
    for (int g = 0; g < 4; ++g) {
        const unsigned go = (g * 32 + phB) & 127;   // warp-dependent k-group rotation
        unsigned a[2][4], b[2][4];
        #pragma unroll
        for (int mb = 0; mb < 2; ++mb)
            ldsm4(a[mb][0], a[mb][1], a[mb][2], a[mb][3], Ab + aOff + go + mb * 2304);
        #pragma unroll
        for (int p = 0; p < 2; ++p)
            ldsm4(b[p][0], b[p][1], b[p][2], b[p][3], Bb + bOff + go + p * 2304);
        #pragma unroll
        for (int mb = 0; mb < 2; ++mb)
            #pragma unroll
            for (int nt = 0; nt < 4; ++nt) {
                const int p = nt >> 1, u = (nt & 1) * 2;
                mma_f16(acc[mb][nt], a[mb], b[p][u], b[p][u + 1]);
            }
    }
}

// =============== kernel A: h = [ relu(conv0_0(x)+b00) | relu(x@W10+b10) ] ===============
__global__ __launch_bounds__(NTHR, 2)
void convA(const int* __restrict__ nbr,
           const float* __restrict__ b00, const float* __restrict__ b10) {
    extern __shared__ unsigned sm[];
    const unsigned sStg = smem_u32(sm);
    const int tid = threadIdx.x, lane = tid & 31, warp = tid >> 5;
    const int wm = warp >> 1, wn = warp & 1;
    const int base = blockIdx.x * MT, rows = min(MT, NPTS - base);
    const int r = tid >> 1, q = tid & 1;
    const bool inval = (r >= rows);
    const int* nbrP = nbr + (size_t)(base + (inval ? 0 : r)) * K3;
    const int selfIdx = inval ? NPTS : (base + r);

    const unsigned aOff = (unsigned)((wm*32 + ((lane>>3)&1)*8 + (lane&7))*144 + ((lane>>4)&1)*16);
    const unsigned bOff = (unsigned)((wn*32 + ((lane>>4)&1)*8 + (lane&7))*144 + ((lane>>3)&1)*16);
    const unsigned phB = (unsigned)(warp & 3) * 32u;
    const unsigned dA0 = sStg + (unsigned)(r*144 + q*64);
    const int qw = q * 16;

    auto stage = [&](unsigned bufD, int kcw, const unsigned* wsrc, int idx) {
        const unsigned sz = (idx < NPTS) ? 16u : 0u;
        const unsigned* src = g_x16 + (size_t)(unsigned)idx * 64u + kcw + qw;
        const unsigned dA = dA0 + bufD;
        cp16(dA,      src,      sz);
        cp16(dA + 16, src + 4,  sz);
        cp16(dA + 32, src + 8,  sz);
        cp16(dA + 48, src + 12, sz);
        const unsigned wD = sStg + bufD + BOFFB + (unsigned)tid * 16u;
        const unsigned* ws = wsrc + tid * 4;
        cp16(wD,            ws,            16u);
        cp16(wD + 256*16u,  ws + 256*4,    16u);
        if (tid < 64) cp16(wD + 512*16u, ws + 512*4, 16u);
        CP_COMMIT();
    };

    float acc0[2][4][4] = {};
    float acc1[2][4][4] = {};

    int id0 = inval ? NPTS : __ldg(&nbrP[0]);
    int idA = inval ? NPTS : __ldg(&nbrP[1]);
    int idB = inval ? NPTS : __ldg(&nbrP[2]);
    stage(0,      0,  g_W00p,          id0);   // stage 0 (tap 0, kc0)
    stage(STGB,   32, g_W00p + 2304,   id0);   // stage 1 (tap 0, kc1)
    stage(2*STGB, 0,  g_W00p + 4608,   idA);   // stage 2 (tap 1, kc0)

    const unsigned* wp = g_W00p + 3 * 2304;
    for (int it = 0; it < 12; ++it) {
        // u=0: mma s=4it (buf0), stage 4it+3 (buf3, kc1, tap 2it+1)
        CP_WAIT2(); __syncthreads();
        int idC = inval ? NPTS : __ldg(&nbrP[2*it + 3]);
        stage(3*STGB, 32, wp, idA);
        mma_stage(sStg,          acc0, aOff, bOff, phB);
        // u=1: mma 4it+1 (buf1), stage 4it+4 (buf0, kc0, tap 2it+2)
        CP_WAIT2(); __syncthreads();
        int idN = inval ? NPTS : __ldg(&nbrP[2*it + 4]);
        stage(0, 0, wp + 2304, idB);
        mma_stage(sStg + STGB,   acc0, aOff, bOff, phB);
        // u=2: mma 4it+2 (buf2), stage 4it+5 (buf1, kc1, tap 2it+2)
        CP_WAIT2(); __syncthreads();
        stage(STGB, 32, wp + 2*2304, idB);
        mma_stage(sStg + 2*STGB, acc0, aOff, bOff, phB);
        // u=3: mma 4it+3 (buf3), stage 4it+6 (buf2, kc0, tap 2it+3)
        CP_WAIT2(); __syncthreads();
        stage(2*STGB, 0, wp + 3*2304, idC);
        mma_stage(sStg + 3*STGB, acc0, aOff, bOff, phB);
        idA = idC; idB = idN;
        wp += 4 * 2304;
    }
    // tail: mma 48..55, stage 51..55 (idA = tap25, idB = tap26)
    CP_WAIT2(); __syncthreads();                               // s=48
    stage(3*STGB, 32, g_W00p + 51*2304, idA);
    mma_stage(sStg,          acc0, aOff, bOff, phB);
    CP_WAIT2(); __syncthreads();                               // s=49
    stage(0, 0, g_W00p + 52*2304, idB);
    mma_stage(sStg + STGB,   acc0, aOff, bOff, phB);
    CP_WAIT2(); __syncthreads();                               // s=50
    stage(STGB, 32, g_W00p + 53*2304, idB);
    mma_stage(sStg + 2*STGB, acc0, aOff, bOff, phB);
    CP_WAIT2(); __syncthreads();                               // s=51
    stage(2*STGB, 0, g_W10p, selfIdx);
    mma_stage(sStg + 3*STGB, acc0, aOff, bOff, phB);
    CP_WAIT2(); __syncthreads();                               // s=52
    stage(3*STGB, 32, g_W10p + 2304, selfIdx);
    mma_stage(sStg,          acc0, aOff, bOff, phB);
    CP_WAIT2(); __syncthreads();                               // s=53
    mma_stage(sStg + STGB,   acc0, aOff, bOff, phB);
    CP_WAIT1(); __syncthreads();                               // s=54
    mma_stage(sStg + 2*STGB, acc1, aOff, bOff, phB);
    CP_WAIT0(); __syncthreads();                               // s=55
    mma_stage(sStg + 3*STGB, acc1, aOff, bOff, phB);

    // epilogue: relu + bias -> h fp16
    #pragma unroll
    for (int mb = 0; mb < 2; ++mb) {
        const int r0 = wm * 32 + mb * 16 + (lane >> 2);
        const int p0 = base + r0, p1 = p0 + 8;
        #pragma unroll
        for (int nt = 0; nt < 4; ++nt) {
            const int col = wn * 32 + nt * 8 + (lane & 3) * 2;
            const float ba0 = __ldg(&b00[col]), ba1 = __ldg(&b00[col + 1]);
            const float bb0 = __ldg(&b10[col]), bb1 = __ldg(&b10[col + 1]);
            if (p0 < NPTS) {
                g_h16[(size_t)p0 * 64 + (col >> 1)] =
                    packh2(fmaxf(acc0[mb][nt][0] + ba0, 0.f), fmaxf(acc0[mb][nt][1] + ba1, 0.f));
                g_h16[(size_t)p0 * 64 + 32 + (col >> 1)] =
                    packh2(fmaxf(acc1[mb][nt][0] + bb0, 0.f), fmaxf(acc1[mb][nt][1] + bb1, 0.f));
            }
            if (p1 < NPTS) {
                g_h16[(size_t)p1 * 64 + (col >> 1)] =
                    packh2(fmaxf(acc0[mb][nt][2] + ba0, 0.f), fmaxf(acc0[mb][nt][3] + ba1, 0.f));
                g_h16[(size_t)p1 * 64 + 32 + (col >> 1)] =
                    packh2(fmaxf(acc1[mb][nt][2] + bb0, 0.f), fmaxf(acc1[mb][nt][3] + bb1, 0.f));
            }
        }
    }
}

// ==== kernel B: out = [conv0_1(h0)+b01 | relu(conv1_1(h1)+b11)@W12+b12] + x ====
__global__ __launch_bounds__(NTHR, 2)
void convB(const int* __restrict__ nbr,
           const float* __restrict__ b01, const float* __restrict__ b11,
           const float* __restrict__ b12, const float* __restrict__ x,
           float* __restrict__ out) {
    extern __shared__ unsigned sm[];
    const unsigned sStg = smem_u32(sm);
    const int tid = threadIdx.x, lane = tid & 31, warp = tid >> 5;
    const int wm = warp >> 1, wn = warp & 1;
    const int base = blockIdx.x * MT, rows = min(MT, NPTS - base);
    const int r = tid >> 1, q = tid & 1;
    const bool inval = (r >= rows);
    const int* nbrP = nbr + (size_t)(base + (inval ? 0 : r)) * K3;

    const unsigned aOff = (unsigned)((wm*32 + ((lane>>3)&1)*8 + (lane&7))*144 + ((lane>>4)&1)*16);
    const unsigned bOff = (unsigned)((wn*32 + ((lane>>4)&1)*8 + (lane&7))*144 + ((lane>>3)&1)*16);
    const unsigned phB = (unsigned)(warp & 3) * 32u;
    const unsigned dA0 = sStg + (unsigned)(r*144 + q*64);
    const int qw = q * 16;

    auto stage = [&](unsigned bufD, int kcw, const unsigned* wsrc, int idx) {
        const unsigned sz = (idx < NPTS) ? 16u : 0u;
        const unsigned* src = g_h16 + (size_t)(unsigned)idx * 64u + kcw + qw;
        const unsigned dA = dA0 + bufD;
        cp16(dA,      src,      sz);
        cp16(dA + 16, src + 4,  sz);
        cp16(dA + 32, src + 8,  sz);
        cp16(dA + 48, src + 12, sz);
        const unsigned wD = sStg + bufD + BOFFB + (unsigned)tid * 16u;
        const unsigned* ws = wsrc + tid * 4;
        cp16(wD,           ws,         16u);
        cp16(wD + 256*16u, ws + 256*4, 16u);
        if (tid < 64) cp16(wD + 512*16u, ws + 512*4, 16u);
        CP_COMMIT();
    };

    float acc0[2][4][4] = {};
    float acc1[2][4][4] = {};

    int id0 = inval ? NPTS : __ldg(&nbrP[0]);
    int idA = inval ? NPTS : __ldg(&nbrP[1]);
    int idB = inval ? NPTS : __ldg(&nbrP[2]);
    stage(0,      0,  g_Wcat,        id0);
    stage(STGB,   32, g_Wcat + 2304, id0);
    stage(2*STGB, 0,  g_Wcat + 4608, idA);

    const unsigned* wp = g_Wcat + 3 * 2304;
    for (int it = 0; it < 12; ++it) {
        CP_WAIT2(); __syncthreads();
        int idC = inval ? NPTS : __ldg(&nbrP[2*it + 3]);
        stage(3*STGB, 32, wp, idA);
        mma_stage(sStg,          acc0, aOff, bOff, phB);
        CP_WAIT2(); __syncthreads();
        int idN = inval ? NPTS : __ldg(&nbrP[2*it + 4]);
        stage(0, 0, wp + 2304, idB);
        mma_stage(sStg + STGB,   acc1, aOff, bOff, phB);
        CP_WAIT2(); __syncthreads();
        stage(STGB, 32, wp + 2*2304, idB);
        mma_stage(sStg + 2*STGB, acc0, aOff, bOff, phB);
        CP_WAIT2(); __syncthreads();
        stage(2*STGB, 0, wp + 3*2304, idC);
        mma_stage(sStg + 3*STGB, acc1, aOff, bOff, phB);
        idA = idC; idB = idN;
        wp += 4 * 2304;
    }
    // tail: mma 48..53, stage 51..53 (idA = tap25, idB = tap26)
    CP_WAIT2(); __syncthreads();                               // s=48
    stage(3*STGB, 32, g_Wcat + 51*2304, idA);
    mma_stage(sStg,          acc0, aOff, bOff, phB);
    CP_WAIT2(); __syncthreads();                               // s=49
    stage(0, 0, g_Wcat + 52*2304, idB);
    mma_stage(sStg + STGB,   acc1, aOff, bOff, phB);
    CP_WAIT2(); __syncthreads();                               // s=50
    stage(STGB, 32, g_Wcat + 53*2304, idB);
    mma_stage(sStg + 2*STGB, acc0, aOff, bOff, phB);
    CP_WAIT2(); __syncthreads();                               // s=51
    mma_stage(sStg + 3*STGB, acc1, aOff, bOff, phB);
    CP_WAIT1(); __syncthreads();                               // s=52
    mma_stage(sStg,          acc0, aOff, bOff, phB);
    CP_WAIT0(); __syncthreads();                               // s=53
    mma_stage(sStg + STGB,   acc1, aOff, bOff, phB);

    // ---- epilogue: store out0 (+b01 +x); stage h1b = relu(acc1+b11) fp16 into buf0 A ----
    #pragma unroll
    for (int mb = 0; mb < 2; ++mb) {
        const int r0 = wm * 32 + mb * 16 + (lane >> 2), r1 = r0 + 8;
        const int p0 = base + r0, p1 = base + r1;
        #pragma unroll
        for (int nt = 0; nt < 4; ++nt) {
            const int col = wn * 32 + nt * 8 + (lane & 3) * 2;
            const float bh0 = __ldg(&b11[col]), bh1 = __ldg(&b11[col + 1]);
            sm[r0 * 36 + (col >> 1)] =
                packh2(fmaxf(acc1[mb][nt][0] + bh0, 0.f), fmaxf(acc1[mb][nt][1] + bh1, 0.f));
            sm[r1 * 36 + (col >> 1)] =
                packh2(fmaxf(acc1[mb][nt][2] + bh0, 0.f), fmaxf(acc1[mb][nt][3] + bh1, 0.f));
            const float bo0 = __ldg(&b01[col]), bo1 = __ldg(&b01[col + 1]);
            if (p0 < NPTS) {
                float2 xv = *(const float2*)(x + (size_t)p0 * 128 + col);
                *(float2*)(out + (size_t)p0 * 128 + col) =
                    make_float2(acc0[mb][nt][0] + bo0 + xv.x, acc0[mb][nt][1] + bo1 + xv.y);
            }
            if (p1 < NPTS) {
                float2 xv = *(const float2*)(x + (size_t)p1 * 128 + col);
                *(float2*)(out + (size_t)p1 * 128 + col) =
                    make_float2(acc0[mb][nt][2] + bo0 + xv.x, acc0[mb][nt][3] + bo1 + xv.y);
            }
        }
    }
    // copy W12 chunk image into buf0 B region
    #pragma unroll
    for (int j = 0; j < 3; ++j) {
        const int i = j * NTHR + tid;
        if (i < 576) ((uint4*)(sm + BOFFB / 4))[i] = ((const uint4*)g_W12p)[i];
    }
    __syncthreads();

    // ---- 1x1 epilogue GEMM: acc2 = h1b @ W12 ----
    float acc2[2][4][4] = {};
    mma_stage(sStg, acc2, aOff, bOff, phB);

    #pragma unroll
    for (int mb = 0; mb < 2; ++mb) {
        const int r0 = wm * 32 + mb * 16 + (lane >> 2);
        const int p0 = base + r0, p1 = p0 + 8;
        #pragma unroll
        for (int nt = 0; nt < 4; ++nt) {
            const int col = wn * 32 + nt * 8 + (lane & 3) * 2;
            const float bv0 = __ldg(&b12[col]), bv1 = __ldg(&b12[col + 1]);
            if (p0 < NPTS) {
                float2 xv = *(const float2*)(x + (size_t)p0 * 128 + 64 + col);
                *(float2*)(out + (size_t)p0 * 128 + 64 + col) =
                    make_float2(acc2[mb][nt][0] + bv0 + xv.x, acc2[mb][nt][1] + bv1 + xv.y);
            }
            if (p1 < NPTS) {
                float2 xv = *(const float2*)(x + (size_t)p1 * 128 + 64 + col);
                *(float2*)(out + (size_t)p1 * 128 + 64 + col) =
                    make_float2(acc2[mb][nt][2] + bv0 + xv.x, acc2[mb][nt][3] + bv1 + xv.y);
            }
        }
    }
}

// ---------------- launch ----------------
extern "C" void kernel_launch(void* const* d_in, const int* in_sizes, int n_in,
                              void* d_out, int out_size) {
    const float* x   = (const float*)d_in[0];
    const int*   nbr = (const int*)  d_in[1];
    const float* W00 = (const float*)d_in[2];
    const float* b00 = (const float*)d_in[3];
    const float* W01 = (const float*)d_in[4];
    const float* b01 = (const float*)d_in[5];
    const float* W10 = (const float*)d_in[6];
    const float* b10 = (const float*)d_in[7];
    const float* W11 = (const float*)d_in[8];
    const float* b11 = (const float*)d_in[9];
    const float* W12 = (const float*)d_in[10];
    const float* b12 = (const float*)d_in[11];
    float* out = (float*)d_out;

    cudaFuncSetAttribute(convA, cudaFuncAttributeMaxDynamicSharedMemorySize, SMEM_BYTES);
    cudaFuncSetAttribute(convB, cudaFuncAttributeMaxDynamicSharedMemorySize, SMEM_BYTES);

    split_x<<<(NPTS * 32 + 255) / 256, 256>>>(x);
    pack_weights<<<(P_TOT + 255) / 256, 256>>>(W00, W01, W11, W10, W12);
    const int grid = (NPTS + MT - 1) / MT;   // 782
    convA<<<grid, NTHR, SMEM_BYTES>>>(nbr, b00, b10);
    convB<<<grid, NTHR, SMEM_BYTES>>>(nbr, b01, b11, b12, x, out);
}